// round 1
// baseline (speedup 1.0000x reference)
#include <cuda_runtime.h>
#include <math.h>

#define TSEQ  4096
#define HID   512
#define NCH   512
#define NHEAD 64
#define NPAIR 256

// -------- device scratch (no allocations allowed) --------
__device__ float g_W1[NCH * HID];     // W1[r][d]   : input projection (Pm @ norm*B)
__device__ float g_Ceff[HID * NCH];   // Ceff[dd][c]: output projection (C @ blkdiag(Pm^T) folded)
__device__ float g_U[NCH * TSEQ];     // U[r][t]    : projected inputs, overwritten by scan output
__device__ float g_Pm[NHEAD * 64];    // expm(P - P^T) per head, row-major 8x8
__device__ float g_gamma[NHEAD];
__device__ float g_norm[NHEAD];
__device__ float g_pair[NPAIR * 4];   // per pair: gamma, cos(theta), sin(theta), theta

// ============================================================
// Setup: per-head expm (scaling & squaring), gamma, pair consts
// ============================================================
__global__ void setup_head(const float* __restrict__ theta_log,
                           const float* __restrict__ P,
                           const float* __restrict__ gamma_log) {
    int h = threadIdx.x;
    if (h >= NHEAD) return;

    float A[64], E[64], Tm[64], Tmp[64];
    // skew-symmetric part, scaled by 1/4 (scaling & squaring, s=2)
    for (int i = 0; i < 8; i++)
        for (int j = 0; j < 8; j++)
            A[i*8+j] = 0.25f * (P[(h*8+i)*8 + j] - P[(h*8+j)*8 + i]);

    for (int i = 0; i < 64; i++) { E[i] = 0.f; Tm[i] = 0.f; }
    for (int i = 0; i < 8; i++)  { E[i*8+i] = 1.f; Tm[i*8+i] = 1.f; }

    for (int k = 1; k <= 12; k++) {
        float invk = 1.f / (float)k;
        for (int i = 0; i < 8; i++)
            for (int j = 0; j < 8; j++) {
                float s = 0.f;
                for (int l = 0; l < 8; l++) s += Tm[i*8+l] * A[l*8+j];
                Tmp[i*8+j] = s * invk;
            }
        for (int i = 0; i < 64; i++) { Tm[i] = Tmp[i]; E[i] += Tm[i]; }
    }
    // square twice: exp(A0) = (exp(A0/4))^4
    for (int i = 0; i < 8; i++)
        for (int j = 0; j < 8; j++) {
            float s = 0.f;
            for (int l = 0; l < 8; l++) s += E[i*8+l] * E[l*8+j];
            Tmp[i*8+j] = s;
        }
    for (int i = 0; i < 8; i++)
        for (int j = 0; j < 8; j++) {
            float s = 0.f;
            for (int l = 0; l < 8; l++) s += Tmp[i*8+l] * Tmp[l*8+j];
            Tm[i*8+j] = s;
        }
    for (int i = 0; i < 64; i++) g_Pm[h*64 + i] = Tm[i];

    float g = expf(-expf(gamma_log[h]));
    g_gamma[h] = g;

    for (int j = 0; j < 4; j++) {
        float th = expf(theta_log[h*4 + j]);
        int p = h*4 + j;
        g_pair[p*4 + 0] = g;
        g_pair[p*4 + 1] = cosf(th);
        g_pair[p*4 + 2] = sinf(th);
        g_pair[p*4 + 3] = th;
    }
}

// per-head trace(B B^T) reduction -> norm
__global__ void setup_norm(const float* __restrict__ Bmat) {
    __shared__ float red[256];
    int h = blockIdx.x;
    int tid = threadIdx.x;
    float acc = 0.f;
    const float* base = Bmat + h * 8 * HID;   // 8*512 = 4096 contiguous floats
    for (int i = tid; i < 8 * HID; i += 256) {
        float v = base[i];
        acc += v * v;
    }
    red[tid] = acc;
    __syncthreads();
    for (int s = 128; s > 0; s >>= 1) {
        if (tid < s) red[tid] += red[tid + s];
        __syncthreads();
    }
    if (tid == 0) {
        float g = g_gamma[h];
        g_norm[h] = sqrtf((1.f - g * g) / red[0]);
    }
}

__global__ void make_W1(const float* __restrict__ Bmat) {
    int idx = blockIdx.x * blockDim.x + threadIdx.x;   // 512*512
    int r = idx >> 9;
    int d = idx & 511;
    int h = r >> 3, N = r & 7;
    const float* pm = &g_Pm[h*64 + N*8];
    float s = 0.f;
#pragma unroll
    for (int n = 0; n < 8; n++) s += pm[n] * Bmat[(h*8 + n) * HID + d];
    g_W1[r * HID + d] = g_norm[h] * s;
}

__global__ void make_Ceff(const float* __restrict__ Cmat) {
    int idx = blockIdx.x * blockDim.x + threadIdx.x;   // 512*512
    int dd = idx >> 9;
    int c  = idx & 511;
    int h = c >> 3, N = c & 7;
    const float* pm = &g_Pm[h*64 + N*8];
    float s = 0.f;
#pragma unroll
    for (int n = 0; n < 8; n++) s += Cmat[dd * NCH + h*8 + n] * pm[n];
    g_Ceff[dd * NCH + c] = s;
}

// ============================================================
// GEMM1: U[r][t] = sum_k W1[r][k] * X[k][t]   (512 x 4096 x 512)
// ============================================================
__global__ __launch_bounds__(256)
void gemm1(const float* __restrict__ X) {
    __shared__ float As[16][68];   // As[k][m]
    __shared__ float Bs[16][68];   // Bs[k][t]
    int t0 = blockIdx.x * 64;
    int m0 = blockIdx.y * 64;
    int tid = threadIdx.x;
    int ty = tid >> 4, tx = tid & 15;

    float acc[4][4];
#pragma unroll
    for (int i = 0; i < 4; i++)
#pragma unroll
        for (int j = 0; j < 4; j++) acc[i][j] = 0.f;

    for (int k0 = 0; k0 < HID; k0 += 16) {
#pragma unroll
        for (int e = 0; e < 4; e++) {
            int idx = tid + e * 256;
            int mm = idx >> 4, kk = idx & 15;
            As[kk][mm] = g_W1[(m0 + mm) * HID + k0 + kk];
        }
#pragma unroll
        for (int e = 0; e < 4; e++) {
            int idx = tid + e * 256;
            int kk = idx >> 6, tt = idx & 63;
            Bs[kk][tt] = X[(k0 + kk) * TSEQ + t0 + tt];
        }
        __syncthreads();
#pragma unroll
        for (int k = 0; k < 16; k++) {
            float4 a = *(const float4*)&As[k][ty * 4];
            float4 b = *(const float4*)&Bs[k][tx * 4];
            float av[4] = {a.x, a.y, a.z, a.w};
            float bv[4] = {b.x, b.y, b.z, b.w};
#pragma unroll
            for (int i = 0; i < 4; i++)
#pragma unroll
                for (int j = 0; j < 4; j++) acc[i][j] += av[i] * bv[j];
        }
        __syncthreads();
    }
#pragma unroll
    for (int i = 0; i < 4; i++)
#pragma unroll
        for (int j = 0; j < 4; j++)
            g_U[(m0 + ty * 4 + i) * TSEQ + t0 + tx * 4 + j] = acc[i][j];
}

// ============================================================
// Scan: per pair p (rows 2p,2p+1 of g_U):
//   y_t = g * R(theta) * y_{t-1} + u_t    (in place)
// Chunked: 128 chunks of 32, carry-scan by thread 0, fixup.
// ============================================================
__global__ __launch_bounds__(128)
void scan_kernel() {
    int p = blockIdx.x;        // 0..255
    int c = threadIdx.x;       // chunk 0..127
    const float g   = g_pair[p*4 + 0];
    const float cth = g_pair[p*4 + 1];
    const float sth = g_pair[p*4 + 2];
    const float th  = g_pair[p*4 + 3];

    float* U0 = g_U + (2*p)     * TSEQ;
    float* U1 = g_U + (2*p + 1) * TSEQ;
    int t0 = c * 32;

    float la[32], lb[32];
    float a = 0.f, b = 0.f;
#pragma unroll
    for (int i = 0; i < 32; i++) {
        float u0 = U0[t0 + i];
        float u1 = U1[t0 + i];
        float na = g * (cth * a - sth * b) + u0;
        float nb = g * (sth * a + cth * b) + u1;
        a = na; b = nb;
        la[i] = a; lb[i] = b;
    }

    __shared__ float sa[128], sb[128], Ga[128], Gb[128];
    sa[c] = a; sb[c] = b;
    __syncthreads();

    if (c == 0) {
        float gl = powf(g, 32.f);
        float th32 = 32.f * th;
        float cl = cosf(th32), sl = sinf(th32);
        float ga = 0.f, gb = 0.f;
        for (int k = 0; k < 128; k++) {
            Ga[k] = ga; Gb[k] = gb;
            float na = gl * (cl * ga - sl * gb) + sa[k];
            float nb = gl * (sl * ga + cl * gb) + sb[k];
            ga = na; gb = nb;
        }
    }
    __syncthreads();

    float va = Ga[c], vb = Gb[c];
#pragma unroll
    for (int i = 0; i < 32; i++) {
        float na = g * (cth * va - sth * vb);
        float nb = g * (sth * va + cth * vb);
        va = na; vb = nb;
        U0[t0 + i] = la[i] + va;
        U1[t0 + i] = lb[i] + vb;
    }
}

// ============================================================
// GEMM2: out[t][dd] = sum_r Ceff[dd][r] * Y[r][t] + D[dd]*X[dd][t]
// ============================================================
__global__ __launch_bounds__(256)
void gemm2(const float* __restrict__ X, const float* __restrict__ Dv,
           float* __restrict__ out) {
    __shared__ float Ys[16][68];   // Ys[r][t]
    __shared__ float Cs[16][68];   // Cs[r][dd]
    int t0 = blockIdx.x * 64;
    int d0 = blockIdx.y * 64;
    int tid = threadIdx.x;
    int ty = tid >> 4, tx = tid & 15;   // ty -> t, tx -> dd

    float acc[4][4];
#pragma unroll
    for (int i = 0; i < 4; i++)
#pragma unroll
        for (int j = 0; j < 4; j++) acc[i][j] = 0.f;

    for (int r0 = 0; r0 < NCH; r0 += 16) {
#pragma unroll
        for (int e = 0; e < 4; e++) {
            int idx = tid + e * 256;
            int rr = idx >> 6, tt = idx & 63;
            Ys[rr][tt] = g_U[(r0 + rr) * TSEQ + t0 + tt];
        }
#pragma unroll
        for (int e = 0; e < 4; e++) {
            int idx = tid + e * 256;
            int dd = idx >> 4, rr = idx & 15;
            Cs[rr][dd] = g_Ceff[(d0 + dd) * NCH + r0 + rr];
        }
        __syncthreads();
#pragma unroll
        for (int k = 0; k < 16; k++) {
            float4 a = *(const float4*)&Ys[k][ty * 4];
            float4 b = *(const float4*)&Cs[k][tx * 4];
            float av[4] = {a.x, a.y, a.z, a.w};
            float bv[4] = {b.x, b.y, b.z, b.w};
#pragma unroll
            for (int i = 0; i < 4; i++)
#pragma unroll
                for (int j = 0; j < 4; j++) acc[i][j] += av[i] * bv[j];
        }
        __syncthreads();
    }
#pragma unroll
    for (int i = 0; i < 4; i++) {
        int t = t0 + ty * 4 + i;
#pragma unroll
        for (int j = 0; j < 4; j++) {
            int dd = d0 + tx * 4 + j;
            out[t * HID + dd] = acc[i][j] + Dv[dd] * X[dd * TSEQ + t];
        }
    }
}

// ============================================================
extern "C" void kernel_launch(void* const* d_in, const int* in_sizes, int n_in,
                              void* d_out, int out_size) {
    const float* X         = (const float*)d_in[0];  // (8,1,512,1,4096) -> batch0 = first 512*4096
    const float* theta_log = (const float*)d_in[1];  // (256,1)
    const float* P         = (const float*)d_in[2];  // (512,8)
    const float* Bmat      = (const float*)d_in[3];  // (512,512)
    const float* Cmat      = (const float*)d_in[4];  // (512,512)
    const float* Dv        = (const float*)d_in[5];  // (512,)
    const float* gamma_log = (const float*)d_in[6];  // (64,)
    float* out = (float*)d_out;                      // (4096,512)

    setup_head<<<1, 64>>>(theta_log, P, gamma_log);
    setup_norm<<<NHEAD, 256>>>(Bmat);
    make_W1<<<(NCH * HID) / 256, 256>>>(Bmat);
    make_Ceff<<<(HID * NCH) / 256, 256>>>(Cmat);

    dim3 g1(TSEQ / 64, NCH / 64);
    gemm1<<<g1, 256>>>(X);

    scan_kernel<<<NPAIR, 128>>>();

    dim3 g2(TSEQ / 64, HID / 64);
    gemm2<<<g2, 256>>>(X, Dv, out);
}

// round 3
// speedup vs baseline: 2.4452x; 2.4452x over previous
#include <cuda_runtime.h>
#include <cuda_bf16.h>
#include <math.h>
#include <stdint.h>

#define TSEQ  4096
#define HID   512
#define NCH   512
#define NHEAD 64
#define NPAIR 256
#define CHUNK 64
#define NCHUNK 64

// ---------------- device scratch (no allocations allowed) ----------------
__device__ __align__(16) __nv_bfloat16 g_W1h[NCH * HID];   // [r][k]
__device__ __align__(16) __nv_bfloat16 g_W1l[NCH * HID];
__device__ __align__(16) __nv_bfloat16 g_Ch[HID * NCH];    // [dd][r]
__device__ __align__(16) __nv_bfloat16 g_Cl[HID * NCH];
__device__ __align__(16) __nv_bfloat16 g_XTh[TSEQ * HID];  // [t][k]
__device__ __align__(16) __nv_bfloat16 g_XTl[TSEQ * HID];
__device__ __align__(16) float g_U[TSEQ * NCH];            // [t][r]
__device__ __align__(16) __nv_bfloat16 g_Yh[TSEQ * NCH];   // [t][r]
__device__ __align__(16) __nv_bfloat16 g_Yl[TSEQ * NCH];
__device__ __align__(16) float g_DX[TSEQ * HID];           // D[d]*X[d][t] as [t][d]
__device__ float g_carry[NCHUNK * NCH];
__device__ float g_Pm[NHEAD * 64];
__device__ float g_gamma[NHEAD];
__device__ float g_norm[NHEAD];
__device__ float g_pair[NPAIR * 8];   // g, cth, sth, th, g64, c64, s64, pad

// ---------------- helpers ----------------
__device__ __forceinline__ uint32_t smem_u32(const void* p) {
    uint32_t a;
    asm("{ .reg .u64 t; cvta.to.shared.u64 t, %1; cvt.u32.u64 %0, t; }"
        : "=r"(a) : "l"(p));
    return a;
}

__device__ __forceinline__ void cp16(uint32_t s, const void* g) {
    asm volatile("cp.async.cg.shared.global [%0], [%1], 16;" :: "r"(s), "l"(g));
}
__device__ __forceinline__ void cp_commit() {
    asm volatile("cp.async.commit_group;");
}
__device__ __forceinline__ void cp_wait1() {
    asm volatile("cp.async.wait_group 1;");
}
__device__ __forceinline__ void cp_wait0() {
    asm volatile("cp.async.wait_group 0;");
}

__device__ __forceinline__ void ldm4(uint32_t* r, uint32_t a) {
    asm volatile("ldmatrix.sync.aligned.m8n8.x4.shared.b16 {%0,%1,%2,%3}, [%4];"
                 : "=r"(r[0]), "=r"(r[1]), "=r"(r[2]), "=r"(r[3]) : "r"(a));
}

__device__ __forceinline__ void mma16816(float* d, const uint32_t* a, const uint32_t* b) {
    asm volatile(
        "mma.sync.aligned.m16n8k16.row.col.f32.bf16.bf16.f32 "
        "{%0,%1,%2,%3}, {%4,%5,%6,%7}, {%8,%9}, {%0,%1,%2,%3};"
        : "+f"(d[0]), "+f"(d[1]), "+f"(d[2]), "+f"(d[3])
        : "r"(a[0]), "r"(a[1]), "r"(a[2]), "r"(a[3]), "r"(b[0]), "r"(b[1]));
}

__device__ __forceinline__ void bf16_split(float x, __nv_bfloat16& h, __nv_bfloat16& l) {
    h = __float2bfloat16_rn(x);
    l = __float2bfloat16_rn(x - __bfloat162float(h));
}

// ============================================================
// Setup: per-head expm (one block per head, element-per-thread matmuls)
// ============================================================
__global__ void setup_head(const float* __restrict__ theta_log,
                           const float* __restrict__ P,
                           const float* __restrict__ gamma_log) {
    int h = blockIdx.x;
    int t = threadIdx.x;           // 0..63
    int i = t >> 3, j = t & 7;
    __shared__ float sA[64], sT[64], sE[64];

    sA[t] = 0.25f * (P[(h*8 + i)*8 + j] - P[(h*8 + j)*8 + i]);
    float id = (i == j) ? 1.f : 0.f;
    sT[t] = id;
    sE[t] = id;
    __syncthreads();

    for (int k = 1; k <= 12; k++) {
        float s = 0.f;
#pragma unroll
        for (int l = 0; l < 8; l++) s += sT[i*8 + l] * sA[l*8 + j];
        s *= (1.f / (float)k);
        __syncthreads();
        sT[t] = s;
        sE[t] += s;
        __syncthreads();
    }
    // square twice: exp(A) = (exp(A/4))^4
    float s = 0.f;
#pragma unroll
    for (int l = 0; l < 8; l++) s += sE[i*8 + l] * sE[l*8 + j];
    __syncthreads();
    sT[t] = s;
    __syncthreads();
    s = 0.f;
#pragma unroll
    for (int l = 0; l < 8; l++) s += sT[i*8 + l] * sT[l*8 + j];
    g_Pm[h*64 + t] = s;

    if (t == 0) {
        float g = expf(-expf(gamma_log[h]));
        g_gamma[h] = g;
    }
    if (t < 4) {
        float g = expf(-expf(gamma_log[h]));
        float g2 = g*g, g4 = g2*g2, g8 = g4*g4, g16 = g8*g8, g32 = g16*g16;
        float g64 = g32*g32;
        float th = expf(theta_log[h*4 + t]);
        float th64 = 64.f * th;
        int p = h*4 + t;
        g_pair[p*8 + 0] = g;
        g_pair[p*8 + 1] = cosf(th);
        g_pair[p*8 + 2] = sinf(th);
        g_pair[p*8 + 3] = th;
        g_pair[p*8 + 4] = g64;
        g_pair[p*8 + 5] = cosf(th64);
        g_pair[p*8 + 6] = sinf(th64);
        g_pair[p*8 + 7] = 0.f;
    }
}

__global__ void setup_norm(const float* __restrict__ Bmat) {
    __shared__ float red[256];
    int h = blockIdx.x;
    int tid = threadIdx.x;
    float acc = 0.f;
    const float* base = Bmat + h * 8 * HID;
    for (int i = tid; i < 8 * HID; i += 256) {
        float v = base[i];
        acc += v * v;
    }
    red[tid] = acc;
    __syncthreads();
    for (int s = 128; s > 0; s >>= 1) {
        if (tid < s) red[tid] += red[tid + s];
        __syncthreads();
    }
    if (tid == 0) {
        float g = g_gamma[h];
        g_norm[h] = sqrtf((1.f - g * g) / red[0]);
    }
}

__global__ void make_W1(const float* __restrict__ Bmat) {
    int idx = blockIdx.x * blockDim.x + threadIdx.x;
    int r = idx >> 9;
    int d = idx & 511;
    int h = r >> 3, N = r & 7;
    const float* pm = &g_Pm[h*64 + N*8];
    float s = 0.f;
#pragma unroll
    for (int n = 0; n < 8; n++) s += pm[n] * Bmat[(h*8 + n) * HID + d];
    float w = g_norm[h] * s;
    __nv_bfloat16 hi, lo; bf16_split(w, hi, lo);
    g_W1h[r * HID + d] = hi;
    g_W1l[r * HID + d] = lo;
}

__global__ void make_Ceff(const float* __restrict__ Cmat) {
    int idx = blockIdx.x * blockDim.x + threadIdx.x;
    int dd = idx >> 9;
    int c  = idx & 511;
    int h = c >> 3, N = c & 7;
    const float* pm = &g_Pm[h*64 + N*8];
    float s = 0.f;
#pragma unroll
    for (int n = 0; n < 8; n++) s += Cmat[dd * NCH + h*8 + n] * pm[n];
    __nv_bfloat16 hi, lo; bf16_split(s, hi, lo);
    g_Ch[dd * NCH + c] = hi;
    g_Cl[dd * NCH + c] = lo;
}

// X[k][t] -> XT[t][k] bf16 splits + DX[t][k] = Dv[k]*X[k][t]
__global__ void transpose_split(const float* __restrict__ X,
                                const float* __restrict__ Dv) {
    __shared__ float t32[32][33];
    int tb = blockIdx.x;
    int kb = blockIdx.y;
    int tx = threadIdx.x & 31, ty = threadIdx.x >> 5;
#pragma unroll
    for (int i = 0; i < 4; i++)
        t32[ty + 8*i][tx] = X[(size_t)(kb*32 + ty + 8*i) * TSEQ + tb*32 + tx];
    __syncthreads();
    float dv = Dv[kb*32 + tx];
#pragma unroll
    for (int i = 0; i < 4; i++) {
        float v = t32[tx][ty + 8*i];
        __nv_bfloat16 hi, lo; bf16_split(v, hi, lo);
        size_t o = (size_t)(tb*32 + ty + 8*i) * HID + kb*32 + tx;
        g_XTh[o] = hi;
        g_XTl[o] = lo;
        g_DX[o] = dv * v;
    }
}

// ============================================================
// bf16 3-MMA split GEMM: C[m][n] = sum_k (Ah+Al)[m][k]*(Bh+Bl)[n][k]
// M=4096, N=512, K=512, tile 128x128, BK=32, cp.async double buffer.
// MODE 1 adds DX[m][n] to the result.
// ============================================================
#define PITCHB 80            // bytes per smem row (32 bf16 + 8 pad)
#define ARRB   (128*PITCHB)  // 10240 per matrix tile
#define STAGEB (4*ARRB)      // 40960 per stage

template <int MODE>
__global__ __launch_bounds__(256, 1)
void gemm_mma(const __nv_bfloat16* __restrict__ Ah, const __nv_bfloat16* __restrict__ Al,
              const __nv_bfloat16* __restrict__ Bh, const __nv_bfloat16* __restrict__ Bl,
              float* __restrict__ Cout, const float* __restrict__ DX) {
    extern __shared__ char smem[];
    uint32_t sb = smem_u32(smem);
    int tid = threadIdx.x, lane = tid & 31, wid = tid >> 5;
    int m0 = blockIdx.x * 128, n0 = blockIdx.y * 128;
    int m_w = (wid & 1) * 64, n_w = (wid >> 1) * 32;

    const __nv_bfloat16* gp[4] = {Ah, Al, Bh, Bl};

    auto load_stage = [&](int s, int k0) {
        uint32_t base = sb + s * STAGEB;
#pragma unroll
        for (int a = 0; a < 4; a++) {
            int row0 = (a < 2) ? m0 : n0;
#pragma unroll
            for (int e = 0; e < 2; e++) {
                int idx = tid + e * 256;
                int row = idx >> 2, q = idx & 3;
                cp16(base + a * ARRB + row * PITCHB + q * 16,
                     gp[a] + (size_t)(row0 + row) * 512 + k0 + q * 8);
            }
        }
    };

    float acc[4][4][4];
#pragma unroll
    for (int i = 0; i < 4; i++)
#pragma unroll
        for (int j = 0; j < 4; j++)
#pragma unroll
            for (int q = 0; q < 4; q++) acc[i][j][q] = 0.f;

    load_stage(0, 0);
    cp_commit();

#pragma unroll 1
    for (int kt = 0; kt < 16; kt++) {
        if (kt < 15) {
            load_stage((kt + 1) & 1, (kt + 1) * 32);
            cp_commit();
            cp_wait1();
        } else {
            cp_wait0();
        }
        __syncthreads();
        uint32_t base = sb + (kt & 1) * STAGEB;
#pragma unroll
        for (int kk = 0; kk < 2; kk++) {
            int cb = kk * 32;   // 16 bf16 * 2B
            uint32_t ah[4][4], al[4][4], bh[2][4], bl[2][4];
#pragma unroll
            for (int i = 0; i < 4; i++) {
                int row = m_w + 16*i + (lane & 15);
                uint32_t ad = base + row * PITCHB + cb + 16 * (lane >> 4);
                ldm4(ah[i], ad);
                ldm4(al[i], ad + ARRB);
            }
#pragma unroll
            for (int j2 = 0; j2 < 2; j2++) {
                int n = n_w + 16*j2 + (lane & 7) + 8 * (lane >> 4);
                uint32_t ad = base + 2 * ARRB + n * PITCHB + cb + 16 * ((lane >> 3) & 1);
                ldm4(bh[j2], ad);
                ldm4(bl[j2], ad + ARRB);
            }
#pragma unroll
            for (int i = 0; i < 4; i++)
#pragma unroll
                for (int j = 0; j < 4; j++) {
                    const uint32_t* Bp_h = &bh[j >> 1][(j & 1) * 2];
                    const uint32_t* Bp_l = &bl[j >> 1][(j & 1) * 2];
                    mma16816(acc[i][j], ah[i], Bp_h);
                    mma16816(acc[i][j], ah[i], Bp_l);
                    mma16816(acc[i][j], al[i], Bp_h);
                }
        }
        __syncthreads();
    }

    // epilogue
    int rh = lane >> 2, c2 = (lane & 3) * 2;
#pragma unroll
    for (int i = 0; i < 4; i++) {
        int row = m0 + m_w + 16*i + rh;
#pragma unroll
        for (int j = 0; j < 4; j++) {
            int col = n0 + n_w + 8*j + c2;
            size_t o0 = (size_t)row * 512 + col;
            size_t o1 = (size_t)(row + 8) * 512 + col;
            float2 v0 = make_float2(acc[i][j][0], acc[i][j][1]);
            float2 v1 = make_float2(acc[i][j][2], acc[i][j][3]);
            if (MODE == 1) {
                float2 d0 = *(const float2*)&DX[o0];
                float2 d1 = *(const float2*)&DX[o1];
                v0.x += d0.x; v0.y += d0.y;
                v1.x += d1.x; v1.y += d1.y;
            }
            *(float2*)&Cout[o0] = v0;
            *(float2*)&Cout[o1] = v1;
        }
    }
}

// ============================================================
// Scan over U[t][r]: y_t = gamma R(theta) y_{t-1} + u_t per pair.
// ============================================================
__global__ __launch_bounds__(256, 1) void scan1() {
    extern __shared__ float su[];   // [CHUNK][NCH]
    int c = blockIdx.x;
    const float4* src = (const float4*)(g_U + (size_t)c * CHUNK * NCH);
    float4* ds = (float4*)su;
    for (int i = threadIdx.x; i < CHUNK * NCH / 4; i += 256) ds[i] = src[i];
    __syncthreads();

    int p = threadIdx.x;
    float g  = g_pair[p*8 + 0];
    float gc = g * g_pair[p*8 + 1];
    float gs = g * g_pair[p*8 + 2];
    float a = 0.f, b = 0.f;
#pragma unroll 4
    for (int i = 0; i < CHUNK; i++) {
        float2 u = *(float2*)&su[i * NCH + 2*p];
        float na = fmaf(gc, a, fmaf(-gs, b, u.x));
        float nb = fmaf(gs, a, fmaf( gc, b, u.y));
        a = na; b = nb;
    }
    *(float2*)&g_carry[c * NCH + 2*p] = make_float2(a, b);
}

__global__ __launch_bounds__(256, 1) void scan3() {
    extern __shared__ float su[];
    int c = blockIdx.x;
    const float4* src = (const float4*)(g_U + (size_t)c * CHUNK * NCH);
    float4* ds = (float4*)su;
    for (int i = threadIdx.x; i < CHUNK * NCH / 4; i += 256) ds[i] = src[i];
    __syncthreads();

    int p = threadIdx.x;
    float g   = g_pair[p*8 + 0];
    float gc  = g * g_pair[p*8 + 1];
    float gs  = g * g_pair[p*8 + 2];
    float gl  = g_pair[p*8 + 4];
    float glc = gl * g_pair[p*8 + 5];
    float gls = gl * g_pair[p*8 + 6];

    float a = 0.f, b = 0.f;
    for (int k = 0; k < c; k++) {
        float2 cr = *(const float2*)&g_carry[k * NCH + 2*p];
        float na = fmaf(glc, a, fmaf(-gls, b, cr.x));
        float nb = fmaf(gls, a, fmaf( glc, b, cr.y));
        a = na; b = nb;
    }

    for (int i = 0; i < CHUNK; i++) {
        float2 u = *(float2*)&su[i * NCH + 2*p];
        float na = fmaf(gc, a, fmaf(-gs, b, u.x));
        float nb = fmaf(gs, a, fmaf( gc, b, u.y));
        a = na; b = nb;
        __nv_bfloat16 ha, la, hb, lb;
        bf16_split(a, ha, la);
        bf16_split(b, hb, lb);
        size_t o = (size_t)(c * CHUNK + i) * NCH + 2*p;
        *(__nv_bfloat162*)&g_Yh[o] = __nv_bfloat162(ha, hb);
        *(__nv_bfloat162*)&g_Yl[o] = __nv_bfloat162(la, lb);
    }
}

// ============================================================
extern "C" void kernel_launch(void* const* d_in, const int* in_sizes, int n_in,
                              void* d_out, int out_size) {
    const float* X         = (const float*)d_in[0];
    const float* theta_log = (const float*)d_in[1];
    const float* P         = (const float*)d_in[2];
    const float* Bmat      = (const float*)d_in[3];
    const float* Cmat      = (const float*)d_in[4];
    const float* Dv        = (const float*)d_in[5];
    const float* gamma_log = (const float*)d_in[6];
    float* out = (float*)d_out;

    const int GEMM_SMEM = 2 * STAGEB;        // 81920
    const int SCAN_SMEM = CHUNK * NCH * 4;   // 131072
    cudaFuncSetAttribute(gemm_mma<0>, cudaFuncAttributeMaxDynamicSharedMemorySize, GEMM_SMEM);
    cudaFuncSetAttribute(gemm_mma<1>, cudaFuncAttributeMaxDynamicSharedMemorySize, GEMM_SMEM);
    cudaFuncSetAttribute(scan1, cudaFuncAttributeMaxDynamicSharedMemorySize, SCAN_SMEM);
    cudaFuncSetAttribute(scan3, cudaFuncAttributeMaxDynamicSharedMemorySize, SCAN_SMEM);

    setup_head<<<NHEAD, 64>>>(theta_log, P, gamma_log);
    setup_norm<<<NHEAD, 256>>>(Bmat);
    make_W1<<<(NCH * HID) / 256, 256>>>(Bmat);
    make_Ceff<<<(HID * NCH) / 256, 256>>>(Cmat);
    transpose_split<<<dim3(TSEQ / 32, HID / 32), 256>>>(X, Dv);

    float* U;   cudaGetSymbolAddress((void**)&U, g_U);
    float* DX;  cudaGetSymbolAddress((void**)&DX, g_DX);
    __nv_bfloat16 *XTh, *XTl, *W1h, *W1l, *Yh, *Yl, *Ch, *Cl;
    cudaGetSymbolAddress((void**)&XTh, g_XTh);
    cudaGetSymbolAddress((void**)&XTl, g_XTl);
    cudaGetSymbolAddress((void**)&W1h, g_W1h);
    cudaGetSymbolAddress((void**)&W1l, g_W1l);
    cudaGetSymbolAddress((void**)&Yh, g_Yh);
    cudaGetSymbolAddress((void**)&Yl, g_Yl);
    cudaGetSymbolAddress((void**)&Ch, g_Ch);
    cudaGetSymbolAddress((void**)&Cl, g_Cl);

    dim3 gg(TSEQ / 128, NCH / 128);   // (32, 4)
    gemm_mma<0><<<gg, 256, GEMM_SMEM>>>(XTh, XTl, W1h, W1l, U, nullptr);

    scan1<<<NCHUNK, 256, SCAN_SMEM>>>();
    scan3<<<NCHUNK, 256, SCAN_SMEM>>>();

    gemm_mma<1><<<gg, 256, GEMM_SMEM>>>(Yh, Yl, Ch, Cl, out, DX);
}